// round 6
// baseline (speedup 1.0000x reference)
#include <cuda_runtime.h>
#include <cuda_bf16.h>
#include <cstdint>
#include <cstdio>

#define BATCH   2
#define SEQ     512
#define DMODEL  512
#define DSTATE  64
#define DCONV   4
#define DINNER  1024
#define NHEADS  16
#define HEADDIM 64
#define DIP     2192      // D_IN_PROJ = 2*1024 + 2*64 + 16
#define CONVDIM 1152      // D_INNER + 2*D_STATE
#define VOCAB   32768
#define VB      4         // virtual batch: [fwd b0, fwd b1, bwd b0, bwd b1]
#define M1      (VB*SEQ)  // 2048
#define MT      (BATCH*SEQ) // 1024

typedef __nv_bfloat16 bf16;

// ---------------- scratch (device globals; no allocation allowed) -------------
__device__ float g_X[MT*DMODEL];
__device__ float g_Xcat[M1*DMODEL];
__device__ float g_Z[M1*DIP];
__device__ float g_xBC[M1*CONVDIM];
__device__ float g_dt[M1*NHEADS];
__device__ float g_dA[M1*NHEADS];
__device__ float g_y[M1*DINNER];
__device__ float g_yn[M1*DINNER];
__device__ float g_Ycat[M1*DMODEL];
__device__ float g_Xf[MT*DMODEL];
__device__ float g_Xb[MT*DMODEL];
__device__ float g_XC[MT*2*DMODEL];
__device__ float g_G[MT*DMODEL];
__device__ float g_H[MT*DMODEL];
__device__ float g_SK[4*M1*DMODEL];     // split-K partials
__device__ int   g_len[BATCH];

// bf16 hi/lo split buffers
__device__ bf16 g_ah[M1*DINNER];        // activation hi (max 2M elems)
__device__ bf16 g_al[M1*DINNER];        // activation lo
__device__ bf16 g_wh[DIP*DMODEL];       // per-layer weight hi (max wi)
__device__ bf16 g_wl[DIP*DMODEL];
__device__ bf16 g_gwh[DMODEL*2*DMODEL]; // aggr weight hi
__device__ bf16 g_gwl[DMODEL*2*DMODEL];
__device__ bf16 g_lwh[VOCAB*DMODEL];    // lm_head weight hi
__device__ bf16 g_lwl[VOCAB*DMODEL];

// ---------------- helpers ----------------------------------------------------
__device__ __forceinline__ float siluf(float x){ return x / (1.f + expf(-x)); }
__device__ __forceinline__ float sigmoidf_(float x){ return 1.f / (1.f + expf(-x)); }

__device__ __forceinline__ float block_reduce_sum(float v){
    __shared__ float sh[8];
    __shared__ float tot;
    #pragma unroll
    for (int o = 16; o > 0; o >>= 1) v += __shfl_xor_sync(0xffffffffu, v, o);
    int w = threadIdx.x >> 5;
    if ((threadIdx.x & 31) == 0) sh[w] = v;
    __syncthreads();
    if (threadIdx.x < 32) {
        float t = (threadIdx.x < 8) ? sh[threadIdx.x] : 0.f;
        #pragma unroll
        for (int o = 4; o > 0; o >>= 1) t += __shfl_xor_sync(0xffffffffu, t, o);
        if (threadIdx.x == 0) tot = t;
    }
    __syncthreads();
    return tot;
}

// ---------------- small kernels ----------------------------------------------
__global__ void k_lengths(const unsigned char* __restrict__ mask){
    int b = blockIdx.x;
    int cnt = 0;
    for (int l = threadIdx.x; l < SEQ; l += blockDim.x)
        cnt += (mask[b*SEQ + l] == 0) ? 1 : 0;
    float total = block_reduce_sum((float)cnt);
    if (threadIdx.x == 0) g_len[b] = (int)(total + 0.5f);
}

__global__ void k_embed(const int* __restrict__ ids, const float* __restrict__ emb){
    int i = blockIdx.x*blockDim.x + threadIdx.x;
    if (i >= MT*DMODEL) return;
    int t = i / DMODEL, d = i % DMODEL;
    g_X[i] = emb[(size_t)ids[t]*DMODEL + d];
}

__global__ void k_build_xcat(){
    int i = blockIdx.x*blockDim.x + threadIdx.x;
    if (i >= M1*DMODEL) return;
    int d = i % DMODEL; int m = i / DMODEL;
    int l = m % SEQ; int vb = m / SEQ;
    float v;
    if (vb < BATCH) {
        v = g_X[((size_t)vb*SEQ + l)*DMODEL + d];
    } else {
        int b = vb - BATCH;
        int len = g_len[b];
        int rl = (l < len) ? (len - 1 - l) : l;
        v = g_X[((size_t)b*SEQ + rl)*DMODEL + d];
    }
    g_Xcat[i] = v;
}

// exact fp32 -> bf16 hi/lo split, 4 elems per thread
__global__ void k_split(const float* __restrict__ s, bf16* __restrict__ hi,
                        bf16* __restrict__ lo, int n){
    int i = (blockIdx.x*blockDim.x + threadIdx.x) * 4;
    if (i >= n) return;
    float4 v = *(const float4*)(s + i);
    bf16 h[4], l[4];
    float vv[4] = {v.x, v.y, v.z, v.w};
    #pragma unroll
    for (int j = 0; j < 4; j++){
        h[j] = __float2bfloat16(vv[j]);
        l[j] = __float2bfloat16(vv[j] - __bfloat162float(h[j]));
    }
    *(uint2*)(hi + i) = *(uint2*)h;
    *(uint2*)(lo + i) = *(uint2*)l;
}

// depthwise causal conv width 4 + silu, reading the xBC slice of g_Z
__global__ void k_conv(const float* __restrict__ cw, const float* __restrict__ cb){
    int i = blockIdx.x*blockDim.x + threadIdx.x;
    if (i >= M1*CONVDIM) return;
    int c = i % CONVDIM; int m = i / CONVDIM; int l = m % SEQ;
    int mbase = m - l;
    float acc = cb[c];
    #pragma unroll
    for (int k = 0; k < DCONV; k++){
        int ls = l - (DCONV-1) + k;
        if (ls >= 0)
            acc += g_Z[(size_t)(mbase + ls)*DIP + DINNER + c] * cw[c*DCONV + k];
    }
    g_xBC[i] = siluf(acc);
}

__global__ void k_dt(const float* __restrict__ dtb, const float* __restrict__ alog){
    int i = blockIdx.x*blockDim.x + threadIdx.x;
    if (i >= M1*NHEADS) return;
    int h = i % NHEADS; int m = i / NHEADS;
    float raw = g_Z[(size_t)m*DIP + DINNER + CONVDIM + h] + dtb[h];
    float dt = (raw > 20.f) ? raw : log1pf(expf(raw));
    float A = -expf(alog[h]);
    g_dt[i] = dt;
    g_dA[i] = expf(dt * A);
}

// SSD scan: one block per (vb, head). State (64x64) in registers (16/thread).
__global__ void __launch_bounds__(256) k_scan(const float* __restrict__ dss){
    int vb = blockIdx.x / NHEADS;
    int h  = blockIdx.x % NHEADS;
    int tid = threadIdx.x;
    int p = tid >> 2;          // 0..63 head-dim row
    int g = tid & 3;           // 0..3 state-dim quarter
    int n0 = g * 16;

    float hst[16];
    #pragma unroll
    for (int j = 0; j < 16; j++) hst[j] = 0.f;

    __shared__ float sB[2][DSTATE];
    __shared__ float sC[2][DSTATE];

    float Dh = dss[h];
    const float* xbase = g_xBC + (size_t)vb*SEQ*CONVDIM;

    if (tid < 64)            sB[0][tid]     = xbase[DINNER + tid];
    else if (tid < 128)      sC[0][tid-64]  = xbase[DINNER + DSTATE + (tid-64)];

    for (int t = 0; t < SEQ; t++){
        __syncthreads();
        int cur = t & 1, nxt = cur ^ 1;
        if (t + 1 < SEQ){
            const float* xb = xbase + (size_t)(t+1)*CONVDIM;
            if (tid < 64)        sB[nxt][tid]    = xb[DINNER + tid];
            else if (tid < 128)  sC[nxt][tid-64] = xb[DINNER + DSTATE + (tid-64)];
        }
        int m = vb*SEQ + t;
        float dt = g_dt[(size_t)m*NHEADS + h];
        float dA = g_dA[(size_t)m*NHEADS + h];
        float xp = xbase[(size_t)t*CONVDIM + h*HEADDIM + p];
        float dtx = dt * xp;
        float acc = 0.f;
        #pragma unroll
        for (int j = 0; j < 16; j++){
            hst[j] = hst[j]*dA + dtx * sB[cur][n0 + j];
            acc   += hst[j] * sC[cur][n0 + j];
        }
        acc += __shfl_xor_sync(0xffffffffu, acc, 1);
        acc += __shfl_xor_sync(0xffffffffu, acc, 2);
        if (g == 0)
            g_y[(size_t)m*DINNER + h*HEADDIM + p] = acc + Dh * xp;
    }
}

// y = rmsnorm(y * silu(z)) * norm_w ; one block per token row (D=1024)
__global__ void __launch_bounds__(256) k_gnorm(const float* __restrict__ nw){
    int m = blockIdx.x;
    float v[4];
    float ss = 0.f;
    #pragma unroll
    for (int j = 0; j < 4; j++){
        int c = threadIdx.x + j*256;
        float z = g_Z[(size_t)m*DIP + c];
        float val = g_y[(size_t)m*DINNER + c] * siluf(z);
        v[j] = val;
        ss += val * val;
    }
    float total = block_reduce_sum(ss);
    float scale = rsqrtf(total / (float)DINNER + 1e-5f);
    #pragma unroll
    for (int j = 0; j < 4; j++){
        int c = threadIdx.x + j*256;
        g_yn[(size_t)m*DINNER + c] = v[j] * scale * nw[c];
    }
}

__global__ void k_unflip(){
    int i = blockIdx.x*blockDim.x + threadIdx.x;
    if (i >= MT*DMODEL) return;
    int d = i % DMODEL; int m = i / DMODEL;
    int l = m % SEQ; int b = m / SEQ;
    float xf = g_Ycat[((size_t)b*SEQ + l)*DMODEL + d];
    int len = g_len[b];
    int rl = (l < len) ? (len - 1 - l) : l;
    float xb = g_Ycat[((size_t)(BATCH + b)*SEQ + rl)*DMODEL + d];
    g_Xf[i] = xf;
    g_Xb[i] = xb;
    g_XC[(size_t)m*(2*DMODEL) + d]          = xf;
    g_XC[(size_t)m*(2*DMODEL) + DMODEL + d] = xb;
}

__global__ void k_combine(){
    int i = blockIdx.x*blockDim.x + threadIdx.x;
    if (i >= MT*DMODEL) return;
    float gg = sigmoidf_(g_G[i]);
    g_X[i] = gg * g_Xf[i] + (1.f - gg) * g_Xb[i];
}

__global__ void __launch_bounds__(256) k_rmsnorm_final(const float* __restrict__ w){
    int m = blockIdx.x;
    float v[2];
    float ss = 0.f;
    #pragma unroll
    for (int j = 0; j < 2; j++){
        int c = threadIdx.x + j*256;
        float x = g_X[(size_t)m*DMODEL + c];
        v[j] = x;
        ss += x * x;
    }
    float total = block_reduce_sum(ss);
    float scale = rsqrtf(total / (float)DMODEL + 1e-5f);
    #pragma unroll
    for (int j = 0; j < 2; j++){
        int c = threadIdx.x + j*256;
        g_H[(size_t)m*DMODEL + c] = v[j] * scale * w[c];
    }
}

// ---------------- bf16x3 tensor-core GEMM ------------------------------------
// C[m,n] = sum_k A[m,k]*B[n,k] with A,B pre-split into bf16 hi/lo pairs.
// Computes Ah*Bh + Ah*Bl + Al*Bh in fp32 accumulators via mma.sync m16n8k16.
// Block tile 128x128, 8 warps (2m x 4n), warp tile 64x32, BK=16 per stage.
// Single smem buffer (padded stride 24 -> conflict-free LDSM), reg prefetch.

#define SPITCH 24   // smem row stride in bf16 (16 data + 8 pad = 48B)

__device__ __forceinline__ void ldsm4(uint32_t (&r)[4], uint32_t addr){
    asm volatile("ldmatrix.sync.aligned.m8n8.x4.shared.b16 {%0,%1,%2,%3}, [%4];"
        : "=r"(r[0]), "=r"(r[1]), "=r"(r[2]), "=r"(r[3]) : "r"(addr));
}

__device__ __forceinline__ void mma_bf16(float (&c)[4], const uint32_t (&a)[4],
                                         const uint32_t b0, const uint32_t b1){
    asm volatile("mma.sync.aligned.m16n8k16.row.col.f32.bf16.bf16.f32 "
        "{%0,%1,%2,%3}, {%4,%5,%6,%7}, {%8,%9}, {%0,%1,%2,%3};"
        : "+f"(c[0]), "+f"(c[1]), "+f"(c[2]), "+f"(c[3])
        : "r"(a[0]), "r"(a[1]), "r"(a[2]), "r"(a[3]), "r"(b0), "r"(b1));
}

__device__ __forceinline__ void bf3_core(
    const bf16* __restrict__ Ah, const bf16* __restrict__ Al,
    const bf16* __restrict__ Bh, const bf16* __restrict__ Bl,
    int N, int K, int m0, int n0, int kbase, int klen,
    float (&acc)[4][4][4])
{
    __shared__ __align__(16) bf16 sAh[128*SPITCH];
    __shared__ __align__(16) bf16 sAl[128*SPITCH];
    __shared__ __align__(16) bf16 sBh[128*SPITCH];
    __shared__ __align__(16) bf16 sBl[128*SPITCH];

    int tid = threadIdx.x;
    int lane = tid & 31, warp = tid >> 5;
    int wm = (warp >> 2) * 64;     // 0 or 64
    int wn = (warp & 3) * 32;      // 0,32,64,96

    // global load mapping: one 16B (8 bf16) chunk per matrix per thread per stage
    int lr = tid >> 1;             // 0..127
    int kc = (tid & 1) * 8;        // 0 or 8

    const bf16* Ah_g = Ah + (size_t)(m0 + lr)*K + kbase + kc;
    const bf16* Al_g = Al + (size_t)(m0 + lr)*K + kbase + kc;
    bool bval = (n0 + lr) < N;
    const bf16* Bh_g = Bh + (size_t)(n0 + lr)*K + kbase + kc;
    const bf16* Bl_g = Bl + (size_t)(n0 + lr)*K + kbase + kc;

    const uint4 z4 = make_uint4(0,0,0,0);
    uint4 ra_h = *(const uint4*)Ah_g;
    uint4 ra_l = *(const uint4*)Al_g;
    uint4 rb_h = bval ? *(const uint4*)Bh_g : z4;
    uint4 rb_l = bval ? *(const uint4*)Bl_g : z4;

    uint32_t sstore = (uint32_t)(lr*SPITCH + kc) * 2;  // byte offset
    uint32_t aAh = (uint32_t)__cvta_generic_to_shared(sAh);
    uint32_t aAl = (uint32_t)__cvta_generic_to_shared(sAl);
    uint32_t aBh = (uint32_t)__cvta_generic_to_shared(sBh);
    uint32_t aBl = (uint32_t)__cvta_generic_to_shared(sBl);

    // ldmatrix lane address offsets (bytes)
    uint32_t a_off = (uint32_t)(((wm + (lane & 15))*SPITCH + (lane >> 4)*8) * 2);
    uint32_t b_off = (uint32_t)(((wn + ((lane >> 4)*8) + (lane & 7))*SPITCH
                                 + ((lane >> 3) & 1)*8) * 2);

    int nk = klen / 16;
    for (int kt = 0; kt < nk; kt++){
        __syncthreads();
        *(uint4*)((char*)sAh + sstore) = ra_h;
        *(uint4*)((char*)sAl + sstore) = ra_l;
        *(uint4*)((char*)sBh + sstore) = rb_h;
        *(uint4*)((char*)sBl + sstore) = rb_l;
        __syncthreads();
        if (kt + 1 < nk){
            ra_h = *(const uint4*)(Ah_g + (kt+1)*16);
            ra_l = *(const uint4*)(Al_g + (kt+1)*16);
            rb_h = bval ? *(const uint4*)(Bh_g + (kt+1)*16) : z4;
            rb_l = bval ? *(const uint4*)(Bl_g + (kt+1)*16) : z4;
        }

        uint32_t ahf[4][4], alf[4][4];
        uint32_t bhf[4][2], blf[4][2];
        #pragma unroll
        for (int mt = 0; mt < 4; mt++){
            ldsm4(ahf[mt], aAh + a_off + mt*(16*SPITCH*2));
            ldsm4(alf[mt], aAl + a_off + mt*(16*SPITCH*2));
        }
        #pragma unroll
        for (int np = 0; np < 2; np++){
            uint32_t r[4];
            ldsm4(r, aBh + b_off + np*(16*SPITCH*2));
            bhf[np*2][0] = r[0]; bhf[np*2][1] = r[1];
            bhf[np*2+1][0] = r[2]; bhf[np*2+1][1] = r[3];
            ldsm4(r, aBl + b_off + np*(16*SPITCH*2));
            blf[np*2][0] = r[0]; blf[np*2][1] = r[1];
            blf[np*2+1][0] = r[2]; blf[np*2+1][1] = r[3];
        }

        #pragma unroll
        for (int mt = 0; mt < 4; mt++)
            #pragma unroll
            for (int nt = 0; nt < 4; nt++){
                mma_bf16(acc[mt][nt], ahf[mt], bhf[nt][0], bhf[nt][1]);
                mma_bf16(acc[mt][nt], ahf[mt], blf[nt][0], blf[nt][1]);
                mma_bf16(acc[mt][nt], alf[mt], bhf[nt][0], bhf[nt][1]);
            }
    }
}

__global__ void __launch_bounds__(256) k_gemm_bf3(
    const bf16* __restrict__ Ah, const bf16* __restrict__ Al,
    const bf16* __restrict__ Bh, const bf16* __restrict__ Bl,
    const float* __restrict__ bias, const float* __restrict__ resid,
    float* __restrict__ C, int M, int N, int K)
{
    int m0 = blockIdx.y * 128, n0 = blockIdx.x * 128;
    float acc[4][4][4];
    #pragma unroll
    for (int a = 0; a < 4; a++)
        #pragma unroll
        for (int b = 0; b < 4; b++)
            #pragma unroll
            for (int c = 0; c < 4; c++) acc[a][b][c] = 0.f;

    bf3_core(Ah, Al, Bh, Bl, N, K, m0, n0, 0, K, acc);

    int lane = threadIdx.x & 31, warp = threadIdx.x >> 5;
    int wm = (warp >> 2) * 64, wn = (warp & 3) * 32;
    int g = lane >> 2, tig = lane & 3;

    #pragma unroll
    for (int mt = 0; mt < 4; mt++){
        #pragma unroll
        for (int nt = 0; nt < 4; nt++){
            int row = m0 + wm + mt*16 + g;
            int col = n0 + wn + nt*8 + tig*2;
            if (col < N){
                float2 v0 = make_float2(acc[mt][nt][0], acc[mt][nt][1]);
                float2 v1 = make_float2(acc[mt][nt][2], acc[mt][nt][3]);
                if (bias){
                    float2 bb = *(const float2*)&bias[col];
                    v0.x += bb.x; v0.y += bb.y; v1.x += bb.x; v1.y += bb.y;
                }
                if (resid){
                    float2 r0 = *(const float2*)&resid[(size_t)row*N + col];
                    float2 r1 = *(const float2*)&resid[(size_t)(row+8)*N + col];
                    v0.x += r0.x; v0.y += r0.y; v1.x += r1.x; v1.y += r1.y;
                }
                *(float2*)&C[(size_t)row*N + col]     = v0;
                *(float2*)&C[(size_t)(row+8)*N + col] = v1;
            }
        }
    }
}

// split-K variant: blockIdx.z slices, partials to g_SK
__global__ void __launch_bounds__(256) k_gemm_bf3_sk(
    const bf16* __restrict__ Ah, const bf16* __restrict__ Al,
    const bf16* __restrict__ Bh, const bf16* __restrict__ Bl,
    int M, int N, int K, int S)
{
    int m0 = blockIdx.y * 128, n0 = blockIdx.x * 128;
    int kchunk = K / S;
    int kbase = blockIdx.z * kchunk;

    float acc[4][4][4];
    #pragma unroll
    for (int a = 0; a < 4; a++)
        #pragma unroll
        for (int b = 0; b < 4; b++)
            #pragma unroll
            for (int c = 0; c < 4; c++) acc[a][b][c] = 0.f;

    bf3_core(Ah, Al, Bh, Bl, N, K, m0, n0, kbase, kchunk, acc);

    int lane = threadIdx.x & 31, warp = threadIdx.x >> 5;
    int wm = (warp >> 2) * 64, wn = (warp & 3) * 32;
    int g = lane >> 2, tig = lane & 3;

    float* Cp = g_SK + (size_t)blockIdx.z * M * N;
    #pragma unroll
    for (int mt = 0; mt < 4; mt++){
        #pragma unroll
        for (int nt = 0; nt < 4; nt++){
            int row = m0 + wm + mt*16 + g;
            int col = n0 + wn + nt*8 + tig*2;
            if (col < N){
                *(float2*)&Cp[(size_t)row*N + col] =
                    make_float2(acc[mt][nt][0], acc[mt][nt][1]);
                *(float2*)&Cp[(size_t)(row+8)*N + col] =
                    make_float2(acc[mt][nt][2], acc[mt][nt][3]);
            }
        }
    }
}

__global__ void k_sk_reduce(const float* __restrict__ bias,
                            const float* __restrict__ resid,
                            float* __restrict__ C, int M, int N, int S)
{
    int i = blockIdx.x*blockDim.x + threadIdx.x;
    if (i >= M*N) return;
    int n = i % N;
    float v = 0.f;
    for (int s = 0; s < S; s++) v += g_SK[(size_t)s*M*N + i];
    if (bias)  v += bias[n];
    if (resid) v += resid[i];
    C[i] = v;
}

// ---------------- driver ------------------------------------------------------
static float* symf(const void* s){ void* p = nullptr; cudaGetSymbolAddress(&p, s); return (float*)p; }
static bf16*  symb(const void* s){ void* p = nullptr; cudaGetSymbolAddress(&p, s); return (bf16*)p; }

extern "C" void kernel_launch(void* const* d_in, const int* in_sizes, int n_in,
                              void* d_out, int out_size)
{
    const int*            ids   = (const int*)d_in[0];
    const unsigned char*  mask  = (const unsigned char*)d_in[1];
    const float*          emb   = (const float*)d_in[2];
    const float*          wi    = (const float*)d_in[3];   // [L, DIP, DMODEL]
    const float*          cw    = (const float*)d_in[4];
    const float*          cb    = (const float*)d_in[5];
    const float*          dtb   = (const float*)d_in[6];
    const float*          alog  = (const float*)d_in[7];
    const float*          dss   = (const float*)d_in[8];
    const float*          nw    = (const float*)d_in[9];
    const float*          wo    = (const float*)d_in[10];  // [L, DMODEL, DINNER]
    const float*          aggw  = (const float*)d_in[11];  // [DMODEL, 2*DMODEL]
    const float*          aggb  = (const float*)d_in[12];
    const float*          nfw   = (const float*)d_in[13];
    const float*          lmw   = (const float*)d_in[14];  // [VOCAB, DMODEL]
    const float*          lmb   = (const float*)d_in[15];
    float*                out   = (float*)d_out;

    float* pXcat = symf(g_Xcat);
    float* pZ    = symf(g_Z);
    float* pyn   = symf(g_yn);
    float* pYcat = symf(g_Ycat);
    float* pXC   = symf(g_XC);
    float* pG    = symf(g_G);
    float* pH    = symf(g_H);
    bf16* pah = symb(g_ah); bf16* pal = symb(g_al);
    bf16* pwh = symb(g_wh); bf16* pwl = symb(g_wl);
    bf16* pgwh = symb(g_gwh); bf16* pgwl = symb(g_gwl);
    bf16* plwh = symb(g_lwh); bf16* plwl = symb(g_lwl);

    k_lengths<<<BATCH, 256>>>(mask);
    k_embed<<<(MT*DMODEL + 255)/256, 256>>>(ids, emb);

    // weight splits shared across layers
    k_split<<<(DMODEL*2*DMODEL/4 + 255)/256, 256>>>(aggw, pgwh, pgwl, DMODEL*2*DMODEL);
    k_split<<<(VOCAB*DMODEL/4 + 255)/256, 256>>>(lmw, plwh, plwl, VOCAB*DMODEL);

    for (int l = 0; l < 2; l++){
        k_build_xcat<<<(M1*DMODEL + 255)/256, 256>>>();

        // in_proj: Z = Xcat @ wi^T   (M1 x DIP, K=DMODEL)
        k_split<<<(M1*DMODEL/4 + 255)/256, 256>>>(pXcat, pah, pal, M1*DMODEL);
        k_split<<<(DIP*DMODEL/4 + 255)/256, 256>>>(wi + (size_t)l*DIP*DMODEL, pwh, pwl, DIP*DMODEL);
        k_gemm_bf3<<<dim3((DIP + 127)/128, M1/128), 256>>>(
            pah, pal, pwh, pwl, nullptr, nullptr, pZ, M1, DIP, DMODEL);

        k_conv<<<(M1*CONVDIM + 255)/256, 256>>>(cw + (size_t)l*CONVDIM*DCONV,
                                                cb + (size_t)l*CONVDIM);
        k_dt<<<(M1*NHEADS + 255)/256, 256>>>(dtb + l*NHEADS, alog + l*NHEADS);
        k_scan<<<VB*NHEADS, 256>>>(dss + l*NHEADS);
        k_gnorm<<<M1, 256>>>(nw + (size_t)l*DINNER);

        // out_proj: Ycat = yn @ wo^T + Xcat   (M1 x DMODEL, K=DINNER), split-K=2
        k_split<<<(M1*DINNER/4 + 255)/256, 256>>>(pyn, pah, pal, M1*DINNER);
        k_split<<<(DMODEL*DINNER/4 + 255)/256, 256>>>(wo + (size_t)l*DMODEL*DINNER, pwh, pwl, DMODEL*DINNER);
        k_gemm_bf3_sk<<<dim3(DMODEL/128, M1/128, 2), 256>>>(
            pah, pal, pwh, pwl, M1, DMODEL, DINNER, 2);
        k_sk_reduce<<<(M1*DMODEL + 255)/256, 256>>>(nullptr, pXcat, pYcat, M1, DMODEL, 2);

        k_unflip<<<(MT*DMODEL + 255)/256, 256>>>();

        // gate: G = [Xf|Xb] @ aggw^T + aggb   (MT x DMODEL, K=2*DMODEL), split-K=4
        k_split<<<(MT*2*DMODEL/4 + 255)/256, 256>>>(pXC, pah, pal, MT*2*DMODEL);
        k_gemm_bf3_sk<<<dim3(DMODEL/128, MT/128, 4), 256>>>(
            pah, pal, pgwh, pgwl, MT, DMODEL, 2*DMODEL, 4);
        k_sk_reduce<<<(MT*DMODEL + 255)/256, 256>>>(aggb, nullptr, pG, MT, DMODEL, 4);

        k_combine<<<(MT*DMODEL + 255)/256, 256>>>();
    }

    k_rmsnorm_final<<<MT, 256>>>(nfw);

    // lm_head: out = H @ lmw^T + lmb   (MT x VOCAB, K=DMODEL)
    k_split<<<(MT*DMODEL/4 + 255)/256, 256>>>(pH, pah, pal, MT*DMODEL);
    k_gemm_bf3<<<dim3(VOCAB/128, MT/128), 256>>>(
        pah, pal, plwh, plwl, lmb, nullptr, out, MT, VOCAB, DMODEL);

    (void)n_in; (void)in_sizes; (void)out_size;
}

// round 9
// speedup vs baseline: 1.4603x; 1.4603x over previous
#include <cuda_runtime.h>
#include <cuda_bf16.h>
#include <cstdint>
#include <cstdio>

#define BATCH   2
#define SEQ     512
#define DMODEL  512
#define DSTATE  64
#define DCONV   4
#define DINNER  1024
#define NHEADS  16
#define HEADDIM 64
#define DIP     2192      // D_IN_PROJ = 2*1024 + 2*64 + 16
#define CONVDIM 1152      // D_INNER + 2*D_STATE
#define VOCAB   32768
#define VB      4         // virtual batch: [fwd b0, fwd b1, bwd b0, bwd b1]
#define M1      (VB*SEQ)  // 2048
#define MT      (BATCH*SEQ) // 1024

typedef __nv_bfloat16 bf16;

// ---------------- scratch (device globals; no allocation allowed) -------------
__device__ float g_X[MT*DMODEL];
__device__ float g_Xcat[M1*DMODEL];
__device__ float g_Z[M1*DIP];
__device__ float g_xBC[M1*CONVDIM];
__device__ float g_dt[M1*NHEADS];
__device__ float g_dA[M1*NHEADS];
__device__ float g_y[M1*DINNER];
__device__ float g_yn[M1*DINNER];
__device__ float g_Ycat[M1*DMODEL];
__device__ float g_Xf[MT*DMODEL];
__device__ float g_Xb[MT*DMODEL];
__device__ float g_XC[MT*2*DMODEL];
__device__ float g_G[MT*DMODEL];
__device__ float g_H[MT*DMODEL];
__device__ float g_SK[4*M1*DMODEL];     // split-K partials
__device__ int   g_len[BATCH];

// bf16 hi/lo split buffers
__device__ bf16 g_ah[M1*DINNER];        // activation hi (max 2M elems)
__device__ bf16 g_al[M1*DINNER];        // activation lo
__device__ bf16 g_wh[DIP*DMODEL];       // per-layer weight hi (max wi)
__device__ bf16 g_wl[DIP*DMODEL];
__device__ bf16 g_gwh[DMODEL*2*DMODEL]; // aggr weight hi
__device__ bf16 g_gwl[DMODEL*2*DMODEL];
__device__ bf16 g_lwh[VOCAB*DMODEL];    // lm_head weight hi
__device__ bf16 g_lwl[VOCAB*DMODEL];

// ---------------- helpers ----------------------------------------------------
__device__ __forceinline__ float siluf(float x){ return x / (1.f + expf(-x)); }
__device__ __forceinline__ float sigmoidf_(float x){ return 1.f / (1.f + expf(-x)); }

__device__ __forceinline__ float block_reduce_sum(float v){
    __shared__ float sh[8];
    __shared__ float tot;
    #pragma unroll
    for (int o = 16; o > 0; o >>= 1) v += __shfl_xor_sync(0xffffffffu, v, o);
    int w = threadIdx.x >> 5;
    if ((threadIdx.x & 31) == 0) sh[w] = v;
    __syncthreads();
    if (threadIdx.x < 32) {
        float t = (threadIdx.x < 8) ? sh[threadIdx.x] : 0.f;
        #pragma unroll
        for (int o = 4; o > 0; o >>= 1) t += __shfl_xor_sync(0xffffffffu, t, o);
        if (threadIdx.x == 0) tot = t;
    }
    __syncthreads();
    return tot;
}

// ---------------- small kernels ----------------------------------------------
__global__ void k_lengths(const unsigned char* __restrict__ mask){
    int b = blockIdx.x;
    int cnt = 0;
    for (int l = threadIdx.x; l < SEQ; l += blockDim.x)
        cnt += (mask[b*SEQ + l] == 0) ? 1 : 0;
    float total = block_reduce_sum((float)cnt);
    if (threadIdx.x == 0) g_len[b] = (int)(total + 0.5f);
}

__global__ void k_embed(const int* __restrict__ ids, const float* __restrict__ emb){
    int i = blockIdx.x*blockDim.x + threadIdx.x;
    if (i >= MT*DMODEL) return;
    int t = i / DMODEL, d = i % DMODEL;
    g_X[i] = emb[(size_t)ids[t]*DMODEL + d];
}

__global__ void k_build_xcat(){
    int i = blockIdx.x*blockDim.x + threadIdx.x;
    if (i >= M1*DMODEL) return;
    int d = i % DMODEL; int m = i / DMODEL;
    int l = m % SEQ; int vb = m / SEQ;
    float v;
    if (vb < BATCH) {
        v = g_X[((size_t)vb*SEQ + l)*DMODEL + d];
    } else {
        int b = vb - BATCH;
        int len = g_len[b];
        int rl = (l < len) ? (len - 1 - l) : l;
        v = g_X[((size_t)b*SEQ + rl)*DMODEL + d];
    }
    g_Xcat[i] = v;
}

// exact fp32 -> bf16 hi/lo split, 4 elems per thread
__global__ void k_split(const float* __restrict__ s, bf16* __restrict__ hi,
                        bf16* __restrict__ lo, int n){
    int i = (blockIdx.x*blockDim.x + threadIdx.x) * 4;
    if (i >= n) return;
    float4 v = *(const float4*)(s + i);
    bf16 h[4], l[4];
    float vv[4] = {v.x, v.y, v.z, v.w};
    #pragma unroll
    for (int j = 0; j < 4; j++){
        h[j] = __float2bfloat16(vv[j]);
        l[j] = __float2bfloat16(vv[j] - __bfloat162float(h[j]));
    }
    *(uint2*)(hi + i) = *(uint2*)h;
    *(uint2*)(lo + i) = *(uint2*)l;
}

// depthwise causal conv width 4 + silu, reading the xBC slice of g_Z
__global__ void k_conv(const float* __restrict__ cw, const float* __restrict__ cb){
    int i = blockIdx.x*blockDim.x + threadIdx.x;
    if (i >= M1*CONVDIM) return;
    int c = i % CONVDIM; int m = i / CONVDIM; int l = m % SEQ;
    int mbase = m - l;
    float acc = cb[c];
    #pragma unroll
    for (int k = 0; k < DCONV; k++){
        int ls = l - (DCONV-1) + k;
        if (ls >= 0)
            acc += g_Z[(size_t)(mbase + ls)*DIP + DINNER + c] * cw[c*DCONV + k];
    }
    g_xBC[i] = siluf(acc);
}

__global__ void k_dt(const float* __restrict__ dtb, const float* __restrict__ alog){
    int i = blockIdx.x*blockDim.x + threadIdx.x;
    if (i >= M1*NHEADS) return;
    int h = i % NHEADS; int m = i / NHEADS;
    float raw = g_Z[(size_t)m*DIP + DINNER + CONVDIM + h] + dtb[h];
    float dt = (raw > 20.f) ? raw : log1pf(expf(raw));
    float A = -expf(alog[h]);
    g_dt[i] = dt;
    g_dA[i] = expf(dt * A);
}

// SSD scan: one block per (vb, head). State (64x64) in registers (16/thread).
__global__ void __launch_bounds__(256) k_scan(const float* __restrict__ dss){
    int vb = blockIdx.x / NHEADS;
    int h  = blockIdx.x % NHEADS;
    int tid = threadIdx.x;
    int p = tid >> 2;          // 0..63 head-dim row
    int g = tid & 3;           // 0..3 state-dim quarter
    int n0 = g * 16;

    float hst[16];
    #pragma unroll
    for (int j = 0; j < 16; j++) hst[j] = 0.f;

    __shared__ float sB[2][DSTATE];
    __shared__ float sC[2][DSTATE];

    float Dh = dss[h];
    const float* xbase = g_xBC + (size_t)vb*SEQ*CONVDIM;

    if (tid < 64)            sB[0][tid]     = xbase[DINNER + tid];
    else if (tid < 128)      sC[0][tid-64]  = xbase[DINNER + DSTATE + (tid-64)];

    for (int t = 0; t < SEQ; t++){
        __syncthreads();
        int cur = t & 1, nxt = cur ^ 1;
        if (t + 1 < SEQ){
            const float* xb = xbase + (size_t)(t+1)*CONVDIM;
            if (tid < 64)        sB[nxt][tid]    = xb[DINNER + tid];
            else if (tid < 128)  sC[nxt][tid-64] = xb[DINNER + DSTATE + (tid-64)];
        }
        int m = vb*SEQ + t;
        float dt = g_dt[(size_t)m*NHEADS + h];
        float dA = g_dA[(size_t)m*NHEADS + h];
        float xp = xbase[(size_t)t*CONVDIM + h*HEADDIM + p];
        float dtx = dt * xp;
        float acc = 0.f;
        #pragma unroll
        for (int j = 0; j < 16; j++){
            hst[j] = hst[j]*dA + dtx * sB[cur][n0 + j];
            acc   += hst[j] * sC[cur][n0 + j];
        }
        acc += __shfl_xor_sync(0xffffffffu, acc, 1);
        acc += __shfl_xor_sync(0xffffffffu, acc, 2);
        if (g == 0)
            g_y[(size_t)m*DINNER + h*HEADDIM + p] = acc + Dh * xp;
    }
}

// y = rmsnorm(y * silu(z)) * norm_w ; one block per token row (D=1024)
__global__ void __launch_bounds__(256) k_gnorm(const float* __restrict__ nw){
    int m = blockIdx.x;
    float v[4];
    float ss = 0.f;
    #pragma unroll
    for (int j = 0; j < 4; j++){
        int c = threadIdx.x + j*256;
        float z = g_Z[(size_t)m*DIP + c];
        float val = g_y[(size_t)m*DINNER + c] * siluf(z);
        v[j] = val;
        ss += val * val;
    }
    float total = block_reduce_sum(ss);
    float scale = rsqrtf(total / (float)DINNER + 1e-5f);
    #pragma unroll
    for (int j = 0; j < 4; j++){
        int c = threadIdx.x + j*256;
        g_yn[(size_t)m*DINNER + c] = v[j] * scale * nw[c];
    }
}

__global__ void k_unflip(){
    int i = blockIdx.x*blockDim.x + threadIdx.x;
    if (i >= MT*DMODEL) return;
    int d = i % DMODEL; int m = i / DMODEL;
    int l = m % SEQ; int b = m / SEQ;
    float xf = g_Ycat[((size_t)b*SEQ + l)*DMODEL + d];
    int len = g_len[b];
    int rl = (l < len) ? (len - 1 - l) : l;
    float xb = g_Ycat[((size_t)(BATCH + b)*SEQ + rl)*DMODEL + d];
    g_Xf[i] = xf;
    g_Xb[i] = xb;
    g_XC[(size_t)m*(2*DMODEL) + d]          = xf;
    g_XC[(size_t)m*(2*DMODEL) + DMODEL + d] = xb;
}

__global__ void k_combine(){
    int i = blockIdx.x*blockDim.x + threadIdx.x;
    if (i >= MT*DMODEL) return;
    float gg = sigmoidf_(g_G[i]);
    g_X[i] = gg * g_Xf[i] + (1.f - gg) * g_Xb[i];
}

__global__ void __launch_bounds__(256) k_rmsnorm_final(const float* __restrict__ w){
    int m = blockIdx.x;
    float v[2];
    float ss = 0.f;
    #pragma unroll
    for (int j = 0; j < 2; j++){
        int c = threadIdx.x + j*256;
        float x = g_X[(size_t)m*DMODEL + c];
        v[j] = x;
        ss += x * x;
    }
    float total = block_reduce_sum(ss);
    float scale = rsqrtf(total / (float)DMODEL + 1e-5f);
    #pragma unroll
    for (int j = 0; j < 2; j++){
        int c = threadIdx.x + j*256;
        g_H[(size_t)m*DMODEL + c] = v[j] * scale * w[c];
    }
}

// ---------------- bf16x3 tensor-core GEMM (mma.sync + cp.async pipeline) -----
// C[m,n] = sum_k A[m,k]*B[n,k] with A,B pre-split into bf16 hi/lo pairs.
// Computes Ah*Bh + Ah*Bl + Al*Bh in fp32 accumulators via mma.sync m16n8k16.
// Block 128x128, 8 warps (2m x 4n), warp tile 64x32, BK=16 per stage.
// 2-stage cp.async double buffer: copies of stage kt+2 overlap MMAs of kt.
// S>1: split-K, partials to g_SK (bias/resid applied in k_sk_reduce).

#define SPITCH 24                 // smem row stride in bf16 (16 data + 8 pad)
#define TILEB  (128*SPITCH*2)     // 6144 B, one 128x16 bf16 tile
#define BUFB   (4*TILEB)          // Ah,Al,Bh,Bl = 24576 B per stage
#define SMEMG  (2*BUFB)           // 49152 B

__device__ __forceinline__ void ldsm4(uint32_t (&r)[4], uint32_t addr){
    asm volatile("ldmatrix.sync.aligned.m8n8.x4.shared.b16 {%0,%1,%2,%3}, [%4];"
        : "=r"(r[0]), "=r"(r[1]), "=r"(r[2]), "=r"(r[3]) : "r"(addr));
}

__device__ __forceinline__ void mma_bf16(float (&c)[4], const uint32_t (&a)[4],
                                         const uint32_t b0, const uint32_t b1){
    asm volatile("mma.sync.aligned.m16n8k16.row.col.f32.bf16.bf16.f32 "
        "{%0,%1,%2,%3}, {%4,%5,%6,%7}, {%8,%9}, {%0,%1,%2,%3};"
        : "+f"(c[0]), "+f"(c[1]), "+f"(c[2]), "+f"(c[3])
        : "r"(a[0]), "r"(a[1]), "r"(a[2]), "r"(a[3]), "r"(b0), "r"(b1));
}

__device__ __forceinline__ void cp16(uint32_t dst, const void* src, bool v){
    int sz = v ? 16 : 0;
    asm volatile("cp.async.cg.shared.global [%0], [%1], 16, %2;"
        :: "r"(dst), "l"(src), "r"(sz) : "memory");
}
#define CP_COMMIT() asm volatile("cp.async.commit_group;" ::: "memory")
#define CP_WAIT(n)  asm volatile("cp.async.wait_group %0;" :: "n"(n) : "memory")

__device__ __forceinline__ uint32_t smem_u32(const void* p){
    uint32_t a;
    asm("{ .reg .u64 t; cvta.to.shared.u64 t, %1; cvt.u32.u64 %0, t; }"
        : "=r"(a) : "l"(p));
    return a;
}

__global__ void __launch_bounds__(256) k_gemm_bf3(
    const bf16* __restrict__ Ah, const bf16* __restrict__ Al,
    const bf16* __restrict__ Bh, const bf16* __restrict__ Bl,
    const float* __restrict__ bias, const float* __restrict__ resid,
    float* __restrict__ C, int M, int N, int K, int S)
{
    extern __shared__ char smc[];
    uint32_t sb = smem_u32(smc);
    int tid = threadIdx.x;
    int lane = tid & 31, warp = tid >> 5;
    int m0 = blockIdx.y * 128, n0 = blockIdx.x * 128;
    int kchunk = K / S;
    int kbase = blockIdx.z * kchunk;
    int nk = kchunk / 16;

    // ---- copy mapping: tile t (0:Ah 1:Al 2:Bh 3:Bl), 4x 16B chunks/thread ----
    int t = tid >> 6, u0 = tid & 63;
    const bf16* src = (t == 0) ? Ah + (size_t)m0*K
                   : (t == 1) ? Al + (size_t)m0*K
                   : (t == 2) ? Bh + (size_t)n0*K
                   :            Bl + (size_t)n0*K;
    int rowlim = (t < 2) ? 128 : (N - n0 < 128 ? N - n0 : 128);
    uint32_t dtile = sb + t*TILEB;

    // precompute per-chunk row/kc and smem offsets
    int rowc[4], kcc[4]; uint32_t soff[4]; bool vld[4];
    #pragma unroll
    for (int j = 0; j < 4; j++){
        int c = u0 + 64*j;
        rowc[j] = c >> 1;
        kcc[j]  = (c & 1) * 8;
        soff[j] = (uint32_t)(rowc[j]*SPITCH + kcc[j]) * 2;
        vld[j]  = rowc[j] < rowlim;
        if (!vld[j]) rowc[j] = 0;   // keep src address in range
    }

    // ---- prologue: stages 0 and 1 in flight ----
    #pragma unroll
    for (int s = 0; s < 2; s++){
        if (s < nk){
            const bf16* sp = src + kbase + s*16;
            uint32_t d0 = dtile + s*BUFB;
            #pragma unroll
            for (int j = 0; j < 4; j++)
                cp16(d0 + soff[j], sp + (size_t)rowc[j]*K + kcc[j], vld[j]);
        }
        CP_COMMIT();
    }
    CP_WAIT(1);
    __syncthreads();

    // ---- warp fragment addressing (validated in R6) ----
    int wm = (warp >> 2) * 64;     // 0 or 64
    int wn = (warp & 3) * 32;      // 0,32,64,96
    uint32_t a_off = (uint32_t)(((wm + (lane & 15))*SPITCH + (lane >> 4)*8) * 2);
    uint32_t b_off = (uint32_t)(((wn + ((lane >> 4)*8) + (lane & 7))*SPITCH
                                 + ((lane >> 3) & 1)*8) * 2);

    float acc[4][4][4];
    #pragma unroll
    for (int a = 0; a < 4; a++)
        #pragma unroll
        for (int b = 0; b < 4; b++)
            #pragma unroll
            for (int c = 0; c < 4; c++) acc[a][b][c] = 0.f;

    for (int kt = 0; kt < nk; kt++){
        int stage = kt & 1;
        uint32_t base = sb + stage*BUFB;
        uint32_t aAh = base, aAl = base + TILEB;
        uint32_t aBh = base + 2*TILEB, aBl = base + 3*TILEB;

        // load fragments
        uint32_t ahf[4][4], alf[4][4];
        uint32_t bhf[4][2], blf[4][2];
        #pragma unroll
        for (int mt = 0; mt < 4; mt++){
            ldsm4(ahf[mt], aAh + a_off + mt*(16*SPITCH*2));
            ldsm4(alf[mt], aAl + a_off + mt*(16*SPITCH*2));
        }
        #pragma unroll
        for (int np = 0; np < 2; np++){
            uint32_t r[4];
            ldsm4(r, aBh + b_off + np*(16*SPITCH*2));
            bhf[np*2][0] = r[0]; bhf[np*2][1] = r[1];
            bhf[np*2+1][0] = r[2]; bhf[np*2+1][1] = r[3];
            ldsm4(r, aBl + b_off + np*(16*SPITCH*2));
            blf[np*2][0] = r[0]; blf[np*2][1] = r[1];
            blf[np*2+1][0] = r[2]; blf[np*2+1][1] = r[3];
        }
        __syncthreads();   // all warps done reading this stage's smem

        // refill this stage's buffer for kt+2 (flies during MMAs below)
        bool refill = (kt + 2 < nk);
        if (refill){
            const bf16* sp = src + kbase + (kt+2)*16;
            uint32_t d0 = dtile + stage*BUFB;
            #pragma unroll
            for (int j = 0; j < 4; j++)
                cp16(d0 + soff[j], sp + (size_t)rowc[j]*K + kcc[j], vld[j]);
            CP_COMMIT();
        }

        // MMAs: 3 split terms
        #pragma unroll
        for (int mt = 0; mt < 4; mt++)
            #pragma unroll
            for (int nt = 0; nt < 4; nt++){
                mma_bf16(acc[mt][nt], ahf[mt], bhf[nt][0], bhf[nt][1]);
                mma_bf16(acc[mt][nt], ahf[mt], blf[nt][0], blf[nt][1]);
                mma_bf16(acc[mt][nt], alf[mt], bhf[nt][0], bhf[nt][1]);
            }

        if (refill) { CP_WAIT(1); } else { CP_WAIT(0); }
        __syncthreads();   // next stage visible to all warps
    }

    // ---- epilogue ----
    int g = lane >> 2, tig = lane & 3;
    float* Cp = (S > 1) ? (g_SK + (size_t)blockIdx.z * M * N) : C;

    #pragma unroll
    for (int mt = 0; mt < 4; mt++){
        #pragma unroll
        for (int nt = 0; nt < 4; nt++){
            int row = m0 + wm + mt*16 + g;
            int col = n0 + wn + nt*8 + tig*2;
            if (col < N){
                float2 v0 = make_float2(acc[mt][nt][0], acc[mt][nt][1]);
                float2 v1 = make_float2(acc[mt][nt][2], acc[mt][nt][3]);
                if (S == 1){
                    if (bias){
                        float2 bb = *(const float2*)&bias[col];
                        v0.x += bb.x; v0.y += bb.y; v1.x += bb.x; v1.y += bb.y;
                    }
                    if (resid){
                        float2 r0 = *(const float2*)&resid[(size_t)row*N + col];
                        float2 r1 = *(const float2*)&resid[(size_t)(row+8)*N + col];
                        v0.x += r0.x; v0.y += r0.y; v1.x += r1.x; v1.y += r1.y;
                    }
                }
                *(float2*)&Cp[(size_t)row*N + col]     = v0;
                *(float2*)&Cp[(size_t)(row+8)*N + col] = v1;
            }
        }
    }
}

__global__ void k_sk_reduce(const float* __restrict__ bias,
                            const float* __restrict__ resid,
                            float* __restrict__ C, int M, int N, int S)
{
    int i = blockIdx.x*blockDim.x + threadIdx.x;
    if (i >= M*N) return;
    int n = i % N;
    float v = 0.f;
    for (int s = 0; s < S; s++) v += g_SK[(size_t)s*M*N + i];
    if (bias)  v += bias[n];
    if (resid) v += resid[i];
    C[i] = v;
}

// ---------------- driver ------------------------------------------------------
static float* symf(const void* s){ void* p = nullptr; cudaGetSymbolAddress(&p, s); return (float*)p; }
static bf16*  symb(const void* s){ void* p = nullptr; cudaGetSymbolAddress(&p, s); return (bf16*)p; }

extern "C" void kernel_launch(void* const* d_in, const int* in_sizes, int n_in,
                              void* d_out, int out_size)
{
    const int*            ids   = (const int*)d_in[0];
    const unsigned char*  mask  = (const unsigned char*)d_in[1];
    const float*          emb   = (const float*)d_in[2];
    const float*          wi    = (const float*)d_in[3];   // [L, DIP, DMODEL]
    const float*          cw    = (const float*)d_in[4];
    const float*          cb    = (const float*)d_in[5];
    const float*          dtb   = (const float*)d_in[6];
    const float*          alog  = (const float*)d_in[7];
    const float*          dss   = (const float*)d_in[8];
    const float*          nw    = (const float*)d_in[9];
    const float*          wo    = (const float*)d_in[10];  // [L, DMODEL, DINNER]
    const float*          aggw  = (const float*)d_in[11];  // [DMODEL, 2*DMODEL]
    const float*          aggb  = (const float*)d_in[12];
    const float*          nfw   = (const float*)d_in[13];
    const float*          lmw   = (const float*)d_in[14];  // [VOCAB, DMODEL]
    const float*          lmb   = (const float*)d_in[15];
    float*                out   = (float*)d_out;

    float* pXcat = symf(g_Xcat);
    float* pZ    = symf(g_Z);
    float* pyn   = symf(g_yn);
    float* pYcat = symf(g_Ycat);
    float* pXC   = symf(g_XC);
    float* pG    = symf(g_G);
    float* pH    = symf(g_H);
    bf16* pah = symb(g_ah); bf16* pal = symb(g_al);
    bf16* pwh = symb(g_wh); bf16* pwl = symb(g_wl);
    bf16* pgwh = symb(g_gwh); bf16* pgwl = symb(g_gwl);
    bf16* plwh = symb(g_lwh); bf16* plwl = symb(g_lwl);

    cudaFuncSetAttribute(k_gemm_bf3, cudaFuncAttributeMaxDynamicSharedMemorySize, SMEMG);

    k_lengths<<<BATCH, 256>>>(mask);
    k_embed<<<(MT*DMODEL + 255)/256, 256>>>(ids, emb);

    // weight splits shared across layers
    k_split<<<(DMODEL*2*DMODEL/4 + 255)/256, 256>>>(aggw, pgwh, pgwl, DMODEL*2*DMODEL);
    k_split<<<(VOCAB*DMODEL/4 + 255)/256, 256>>>(lmw, plwh, plwl, VOCAB*DMODEL);

    for (int l = 0; l < 2; l++){
        k_build_xcat<<<(M1*DMODEL + 255)/256, 256>>>();

        // in_proj: Z = Xcat @ wi^T   (M1 x DIP, K=DMODEL)
        k_split<<<(M1*DMODEL/4 + 255)/256, 256>>>(pXcat, pah, pal, M1*DMODEL);
        k_split<<<(DIP*DMODEL/4 + 255)/256, 256>>>(wi + (size_t)l*DIP*DMODEL, pwh, pwl, DIP*DMODEL);
        k_gemm_bf3<<<dim3((DIP + 127)/128, M1/128, 1), 256, SMEMG>>>(
            pah, pal, pwh, pwl, nullptr, nullptr, pZ, M1, DIP, DMODEL, 1);

        k_conv<<<(M1*CONVDIM + 255)/256, 256>>>(cw + (size_t)l*CONVDIM*DCONV,
                                                cb + (size_t)l*CONVDIM);
        k_dt<<<(M1*NHEADS + 255)/256, 256>>>(dtb + l*NHEADS, alog + l*NHEADS);
        k_scan<<<VB*NHEADS, 256>>>(dss + l*NHEADS);
        k_gnorm<<<M1, 256>>>(nw + (size_t)l*DINNER);

        // out_proj: Ycat = yn @ wo^T + Xcat   (M1 x DMODEL, K=DINNER), split-K=2
        k_split<<<(M1*DINNER/4 + 255)/256, 256>>>(pyn, pah, pal, M1*DINNER);
        k_split<<<(DMODEL*DINNER/4 + 255)/256, 256>>>(wo + (size_t)l*DMODEL*DINNER, pwh, pwl, DMODEL*DINNER);
        k_gemm_bf3<<<dim3(DMODEL/128, M1/128, 2), 256, SMEMG>>>(
            pah, pal, pwh, pwl, nullptr, nullptr, nullptr, M1, DMODEL, DINNER, 2);
        k_sk_reduce<<<(M1*DMODEL + 255)/256, 256>>>(nullptr, pXcat, pYcat, M1, DMODEL, 2);

        k_unflip<<<(MT*DMODEL + 255)/256, 256>>>();

        // gate: G = [Xf|Xb] @ aggw^T + aggb   (MT x DMODEL, K=2*DMODEL), split-K=4
        k_split<<<(MT*2*DMODEL/4 + 255)/256, 256>>>(pXC, pah, pal, MT*2*DMODEL);
        k_gemm_bf3<<<dim3(DMODEL/128, MT/128, 4), 256, SMEMG>>>(
            pah, pal, pgwh, pgwl, nullptr, nullptr, nullptr, MT, DMODEL, 2*DMODEL, 4);
        k_sk_reduce<<<(MT*DMODEL + 255)/256, 256>>>(aggb, nullptr, pG, MT, DMODEL, 4);

        k_combine<<<(MT*DMODEL + 255)/256, 256>>>();
    }

    k_rmsnorm_final<<<MT, 256>>>(nfw);

    // lm_head: out = H @ lmw^T + lmb   (MT x VOCAB, K=DMODEL)
    k_split<<<(MT*DMODEL/4 + 255)/256, 256>>>(pH, pah, pal, MT*DMODEL);
    k_gemm_bf3<<<dim3(VOCAB/128, MT/128, 1), 256, SMEMG>>>(
        pah, pal, plwh, plwl, lmb, nullptr, out, MT, VOCAB, DMODEL, 1);

    (void)n_in; (void)in_sizes; (void)out_size;
}